// round 13
// baseline (speedup 1.0000x reference)
#include <cuda_runtime.h>
#include <cuda_bf16.h>
#include <cstdint>

// Problem constants
#define BB 32
#define SS 512
#define EE 300
#define EP 304          // padded K
#define HH 128
#define G4 512          // 4*H
#define NN 1024         // fused fwd+bwd gate width

// Scratch (device globals; allocation-free rule)
__device__ float g_X[(size_t)BB * SS * EP];        // padded embeddings [16384][304]
__device__ float g_W[(size_t)EP * NN];             // packed input weights W[k][n], n permuted
__device__ float g_bias[NN];
__device__ float g_G[(size_t)BB * SS * NN];        // gate preactivations [16384][1024]
__device__ float g_pooled[BB * 2 * HH];            // [b][dir*128+idx]

// ---------- helpers ----------
__device__ __forceinline__ unsigned long long fma2(unsigned long long a,
                                                   unsigned long long b,
                                                   unsigned long long c) {
    unsigned long long d;
    asm("fma.rn.f32x2 %0, %1, %2, %3;" : "=l"(d) : "l"(a), "l"(b), "l"(c));
    return d;
}
__device__ __forceinline__ float2 unpk(unsigned long long v) {
    float2 r;
    asm("mov.b64 {%0, %1}, %2;" : "=f"(r.x), "=f"(r.y) : "l"(v));
    return r;
}
__device__ __forceinline__ float tanh_ap(float x) {
    float y;
    asm("tanh.approx.f32 %0, %1;" : "=f"(y) : "f"(x));
    return y;
}
__device__ __forceinline__ unsigned int smem_u32(const void* p) {
    unsigned int a;
    asm("{ .reg .u64 t; cvta.to.shared.u64 t, %1; cvt.u32.u64 %0, t; }"
        : "=r"(a) : "l"(p));
    return a;
}
__device__ __forceinline__ uint32_t f2tf32(float f) {
    uint32_t u;
    asm("cvt.rna.tf32.f32 %0, %1;" : "=r"(u) : "f"(f));
    return u;
}
__device__ __forceinline__ void mma_tf32(float* c,
                                         uint32_t a0, uint32_t a1, uint32_t a2, uint32_t a3,
                                         uint32_t b0, uint32_t b1) {
    asm volatile(
        "mma.sync.aligned.m16n8k8.row.col.f32.tf32.tf32.f32 "
        "{%0,%1,%2,%3}, {%4,%5,%6,%7}, {%8,%9}, {%0,%1,%2,%3};"
        : "+f"(c[0]), "+f"(c[1]), "+f"(c[2]), "+f"(c[3])
        : "r"(a0), "r"(a1), "r"(a2), "r"(a3), "r"(b0), "r"(b1));
}
// mbarrier wait (parity), acquire.cta
__device__ __forceinline__ void mbar_wait(unsigned int mb, unsigned int par) {
    unsigned int done;
    asm volatile(
        "{\n\t.reg .pred P;\n\t"
        "mbarrier.try_wait.parity.acquire.cta.shared::cta.b64 P, [%1], %2;\n\t"
        "selp.b32 %0, 1, 0, P;\n\t}"
        : "=r"(done) : "r"(mb), "r"(par) : "memory");
    if (!done) {
        asm volatile(
            "{\n\t.reg .pred P;\n"
            "WL%=:\n\t"
            "mbarrier.try_wait.parity.acquire.cta.shared::cta.b64 P, [%0], %1, 0x989680;\n\t"
            "@P bra.uni WD%=;\n\t"
            "bra.uni WL%=;\n"
            "WD%=:\n\t}"
            :: "r"(mb), "r"(par) : "memory");
    }
}
// 64-element dot: 32 packed f32x2 weights x contiguous h vector in smem
__device__ __forceinline__ float dot64(const unsigned long long* wreg,
                                       const float* hvec) {
    const ulonglong2* hq = (const ulonglong2*)hvec;
    unsigned long long a0 = 0ull, a1 = 0ull, a2 = 0ull, a3 = 0ull;
#pragma unroll
    for (int m = 0; m < 8; m++) {
        ulonglong2 q0 = hq[2 * m], q1 = hq[2 * m + 1];
        a0 = fma2(wreg[4 * m + 0], q0.x, a0);
        a1 = fma2(wreg[4 * m + 1], q0.y, a1);
        a2 = fma2(wreg[4 * m + 2], q1.x, a2);
        a3 = fma2(wreg[4 * m + 3], q1.y, a3);
    }
    float2 s0 = unpk(a0), s1 = unpk(a1), s2 = unpk(a2), s3 = unpk(a3);
    return ((s0.x + s0.y) + (s1.x + s1.y)) + ((s2.x + s2.y) + (s3.x + s3.y));
}

// ---------- Kernel 1: pack input-projection weights + bias ----------
// Column permutation: packed col n = dir*512 + hu*4 + gi.
__global__ void pack_w_kernel(const float* __restrict__ Wih_f,
                              const float* __restrict__ Wih_b,
                              const float* __restrict__ b_f,
                              const float* __restrict__ b_b) {
    int idx = blockIdx.x * 256 + threadIdx.x;
    if (idx < EP * NN) {
        int k = idx >> 10;
        int n = idx & 1023;
        int d = n >> 9, r = n & 511;
        int hu = r >> 2, gi = r & 3;
        int srow = gi * HH + hu;           // source gate row in Wih layout
        float v = 0.0f;
        if (k < EE) v = d ? Wih_b[srow * EE + k] : Wih_f[srow * EE + k];
        g_W[idx] = v;
    }
    if (idx < NN) {
        int d = idx >> 9, r = idx & 511;
        int hu = r >> 2, gi = r & 3;
        int srow = gi * HH + hu;
        g_bias[idx] = d ? b_b[srow] : b_f[srow];
    }
}

// ---------- Kernel 2: embeddings with dep-mean blend ----------
__global__ void embed_kernel(const int* __restrict__ word_ids,
                             const int* __restrict__ deps_ids,
                             const float* __restrict__ word_table,
                             const float* __restrict__ dep_table) {
    int bs = blockIdx.x;           // 0..16383
    int b = bs >> 9;
    int s = bs & 511;
    int wid = word_ids[b * (3 * SS) + SS + s];

    int ids[8];
    float cnt = 0.0f;
#pragma unroll
    for (int d = 0; d < 8; d++) {
        ids[d] = deps_ids[bs * 8 + d];
        if (ids[d] > 1) cnt += 1.0f;   // PAD=0, UNK=1
    }
    float inv = (cnt > 0.0f) ? 0.5f / cnt : 0.0f;
    float wscale = (cnt > 0.0f) ? 0.5f : 1.0f;

    for (int e = threadIdx.x; e < EP; e += 128) {
        float v = 0.0f;
        if (e < EE) {
            float w = word_table[(size_t)wid * EE + e];
            float sum = 0.0f;
#pragma unroll
            for (int d = 0; d < 8; d++) {
                if (ids[d] > 1) sum += dep_table[ids[d] * EE + e];
            }
            v = wscale * w + inv * sum;
        }
        g_X[(size_t)bs * EP + e] = v;
    }
}

// ---------- Kernel 3: tf32 tensor-core GEMM G = X @ W + bias ----------
__global__ void __launch_bounds__(256, 2) gemm_tc_kernel() {
    __shared__ uint32_t As[128][20];
    __shared__ uint32_t Bs[16][136];

    int tid = threadIdx.x;
    int bm = blockIdx.x * 128;
    int bn = blockIdx.y * 128;
    int lane = tid & 31, wid = tid >> 5;
    int wm = wid & 3, wn = wid >> 2;
    int g = lane >> 2, tg = lane & 3;

    float acc[2][8][4];
#pragma unroll
    for (int i = 0; i < 2; i++)
#pragma unroll
        for (int j = 0; j < 8; j++)
#pragma unroll
            for (int q = 0; q < 4; q++) acc[i][j][q] = 0.0f;

    int aIdx0 = tid * 2, aIdx1 = tid * 2 + 1;
    int am0 = aIdx0 >> 2, ak0 = (aIdx0 & 3) << 2;
    int am1 = aIdx1 >> 2, ak1 = (aIdx1 & 3) << 2;
    int bk0 = aIdx0 >> 5, bn0 = (aIdx0 & 31) << 2;
    int bk1 = aIdx1 >> 5, bn1 = (aIdx1 & 31) << 2;

    float4 aR0, aR1, bR0, bR1;
    aR0 = *(const float4*)(g_X + (size_t)(bm + am0) * EP + ak0);
    aR1 = *(const float4*)(g_X + (size_t)(bm + am1) * EP + ak1);
    bR0 = *(const float4*)(g_W + (size_t)bk0 * NN + bn + bn0);
    bR1 = *(const float4*)(g_W + (size_t)bk1 * NN + bn + bn1);

    for (int k0 = 0; k0 < EP; k0 += 16) {
        __syncthreads();
        {
            uint4 u;
            u.x = f2tf32(aR0.x); u.y = f2tf32(aR0.y); u.z = f2tf32(aR0.z); u.w = f2tf32(aR0.w);
            *(uint4*)&As[am0][ak0] = u;
            u.x = f2tf32(aR1.x); u.y = f2tf32(aR1.y); u.z = f2tf32(aR1.z); u.w = f2tf32(aR1.w);
            *(uint4*)&As[am1][ak1] = u;
            u.x = f2tf32(bR0.x); u.y = f2tf32(bR0.y); u.z = f2tf32(bR0.z); u.w = f2tf32(bR0.w);
            *(uint4*)&Bs[bk0][bn0] = u;
            u.x = f2tf32(bR1.x); u.y = f2tf32(bR1.y); u.z = f2tf32(bR1.z); u.w = f2tf32(bR1.w);
            *(uint4*)&Bs[bk1][bn1] = u;
        }
        __syncthreads();

        if (k0 + 16 < EP) {
            aR0 = *(const float4*)(g_X + (size_t)(bm + am0) * EP + k0 + 16 + ak0);
            aR1 = *(const float4*)(g_X + (size_t)(bm + am1) * EP + k0 + 16 + ak1);
            bR0 = *(const float4*)(g_W + (size_t)(k0 + 16 + bk0) * NN + bn + bn0);
            bR1 = *(const float4*)(g_W + (size_t)(k0 + 16 + bk1) * NN + bn + bn1);
        }

#pragma unroll
        for (int kp = 0; kp < 16; kp += 8) {
            uint32_t af[2][4];
#pragma unroll
            for (int i = 0; i < 2; i++) {
                int mr = wm * 32 + i * 16 + g;
                af[i][0] = As[mr][kp + tg];
                af[i][1] = As[mr + 8][kp + tg];
                af[i][2] = As[mr][kp + tg + 4];
                af[i][3] = As[mr + 8][kp + tg + 4];
            }
#pragma unroll
            for (int j = 0; j < 8; j++) {
                int nc = wn * 64 + j * 8 + g;
                uint32_t b0 = Bs[kp + tg][nc];
                uint32_t b1 = Bs[kp + tg + 4][nc];
#pragma unroll
                for (int i = 0; i < 2; i++)
                    mma_tf32(acc[i][j], af[i][0], af[i][1], af[i][2], af[i][3], b0, b1);
            }
        }
    }

#pragma unroll
    for (int j = 0; j < 8; j++) {
        int col = bn + wn * 64 + j * 8 + tg * 2;
        float bc0 = g_bias[col], bc1 = g_bias[col + 1];
#pragma unroll
        for (int i = 0; i < 2; i++) {
            int row = bm + wm * 32 + i * 16 + g;
            *(float2*)(g_G + (size_t)row * NN + col) =
                make_float2(acc[i][j][0] + bc0, acc[i][j][1] + bc1);
            *(float2*)(g_G + (size_t)(row + 8) * NN + col) =
                make_float2(acc[i][j][2] + bc0, acc[i][j][3] + bc1);
        }
    }
}

// ---------- Kernel 4: LSTM scan — 2 chains per cluster (shared Whh) ----------
// R12 protocol per chain, two independent chains (batches 2k, 2k+1 of the
// same direction) interleaved per superstep so chain A's DSMEM transit
// overlaps chain B's compute and vice versa. Weights shared (same dir).
__global__ void __launch_bounds__(512, 1) __cluster_dims__(2, 1, 1)
lstm_scan_kernel(const float* __restrict__ Whh_f, const float* __restrict__ Whh_b) {
    __shared__ float hbufA[2 * 64], hbufB[2 * 64];   // local units' h, dbl-buffered
    __shared__ float pbufA[2 * 256], pbufB[2 * 256]; // peer partials
    __shared__ __align__(8) unsigned long long bars[4];   // [chain A ph0,ph1, chain B ph0,ph1]

    int tid = threadIdx.x;
    int l = tid & 31;
    int hu = tid >> 2;                   // global hidden unit 0..127
    int gi = tid & 3;                    // gate (i,f,g,o)

    unsigned int rank;
    asm("mov.u32 %0, %%cluster_ctarank;" : "=r"(rank));
    unsigned int peer = rank ^ 1u;

    bool own = ((unsigned)(tid >> 8) == rank);
    int k = blockIdx.x >> 1;             // cluster id 0..15
    int bA = 2 * k, bB = 2 * k + 1;
    int dir = blockIdx.y;
    const float* Whh = dir ? Whh_b : Whh_f;

    // 64 register-resident weights: row srow, columns [rank*64, +64) — shared by both chains
    int srow = gi * HH + hu;
    const unsigned long long* wr =
        (const unsigned long long*)(Whh + (size_t)srow * HH + rank * 64);
    unsigned long long wreg[32];
#pragma unroll
    for (int m = 0; m < 32; m++) wreg[m] = wr[m];

    if (tid < 128) { hbufA[tid] = 0.0f; hbufB[tid] = 0.0f; }
    pbufA[tid] = 0.0f;
    pbufB[tid] = 0.0f;
    if (tid < 4) {
        unsigned int b0 = smem_u32(&bars[0]) + (unsigned)(tid * 8);
        asm volatile("mbarrier.init.shared.b64 [%0], 1;" :: "r"(b0) : "memory");
    }
    __syncthreads();
    asm volatile("barrier.cluster.arrive.aligned;" ::: "memory");
    asm volatile("barrier.cluster.wait.aligned;" ::: "memory");

    unsigned int pbA_l = smem_u32(pbufA);
    unsigned int pbB_l = smem_u32(pbufB);
    unsigned int bar_l = smem_u32(&bars[0]);
    unsigned int pbA_r, pbB_r, bar_r;
    asm("mapa.shared::cluster.u32 %0, %1, %2;" : "=r"(pbA_r) : "r"(pbA_l), "r"(peer));
    asm("mapa.shared::cluster.u32 %0, %1, %2;" : "=r"(pbB_r) : "r"(pbB_l), "r"(peer));
    asm("mapa.shared::cluster.u32 %0, %1, %2;" : "=r"(bar_r) : "r"(bar_l), "r"(peer));

    // permuted G column = dir*512 + tid
    long stepoff = dir ? -(long)NN : (long)NN;
    const float* gpA = dir ? (g_G + ((size_t)(bA * SS + SS - 1)) * NN + G4 + tid)
                           : (g_G + ((size_t)(bA * SS)) * NN + tid);
    const float* gpB = dir ? (g_G + ((size_t)(bB * SS + SS - 1)) * NN + G4 + tid)
                           : (g_G + ((size_t)(bB * SS)) * NN + tid);

    float gpreA = own ? __ldg(gpA) : 0.0f;
    float gpreB = own ? __ldg(gpB) : 0.0f;
    gpA += stepoff; gpB += stepoff;

    float cA = 0.0f, cB = 0.0f, hmA = -1e30f, hmB = -1e30f;

    int p = 0;
    if (own) {
        // ======================= ACT role =======================
        int sl = tid & 255;
        for (int t = 0; t < SS; t++) {
            unsigned int ph = (unsigned)((t & 1) * 8);
            unsigned int par = (t >> 1) & 1;
            // arm both chains' barriers (two distinct act threads)
            if (sl == 0) {
                asm volatile("mbarrier.arrive.expect_tx.shared.b64 _, [%0], 1024;"
                             :: "r"(bar_l + ph) : "memory");
            } else if (sl == 1) {
                asm volatile("mbarrier.arrive.expect_tx.shared.b64 _, [%0], 1024;"
                             :: "r"(bar_l + 16 + ph) : "memory");
            }

            float gnA = 0.0f, gnB = 0.0f;
            if (t + 1 < SS) { gnA = __ldg(gpA); gnB = __ldg(gpB); }
            gpA += stepoff; gpB += stepoff;

            // own partial dots (local h) for both chains
            float pA = dot64(wreg, hbufA + p * 64);
            float pB = dot64(wreg, hbufB + p * 64);

            // ---- chain A ----
            mbar_wait(bar_l + ph, par);
            {
                float s = pA + pbufA[(t & 1) * 256 + sl] + gpreA;
                float targ = (gi == 2) ? s : 0.5f * s;
                float tv = tanh_ap(targ);
                int base = l & ~3;
                float ti = __shfl_sync(0xffffffffu, tv, base + 0);
                float tf = __shfl_sync(0xffffffffu, tv, base + 1);
                float tg = __shfl_sync(0xffffffffu, tv, base + 2);
                float to = __shfl_sync(0xffffffffu, tv, base + 3);
                float ig = fmaf(0.5f, ti, 0.5f);
                float fg = fmaf(0.5f, tf, 0.5f);
                float og = fmaf(0.5f, to, 0.5f);
                cA = fg * cA + ig * tg;
                float hh = og * tanh_ap(cA);
                hmA = fmaxf(hmA, hh);
                if (gi == 0) hbufA[(p ^ 1) * 64 + (hu & 63)] = hh;
            }
            // ---- chain B ----
            mbar_wait(bar_l + 16 + ph, par);
            {
                float s = pB + pbufB[(t & 1) * 256 + sl] + gpreB;
                float targ = (gi == 2) ? s : 0.5f * s;
                float tv = tanh_ap(targ);
                int base = l & ~3;
                float ti = __shfl_sync(0xffffffffu, tv, base + 0);
                float tf = __shfl_sync(0xffffffffu, tv, base + 1);
                float tg = __shfl_sync(0xffffffffu, tv, base + 2);
                float to = __shfl_sync(0xffffffffu, tv, base + 3);
                float ig = fmaf(0.5f, ti, 0.5f);
                float fg = fmaf(0.5f, tf, 0.5f);
                float og = fmaf(0.5f, to, 0.5f);
                cB = fg * cB + ig * tg;
                float hh = og * tanh_ap(cB);
                hmB = fmaxf(hmB, hh);
                if (gi == 0) hbufB[(p ^ 1) * 64 + (hu & 63)] = hh;
            }
            // release producers; act-internal rendezvous
            asm volatile("bar.arrive 1, 512;" ::: "memory");
            asm volatile("bar.sync 2, 256;" ::: "memory");
            p ^= 1;
            gpreA = gnA; gpreB = gnB;
        }
        if (gi == 0) {
            g_pooled[bA * 256 + dir * HH + hu] = hmA;
            g_pooled[bB * 256 + dir * HH + hu] = hmB;
        }
    } else {
        // ===================== PRODUCER role =====================
        int sl = tid & 255;
        for (int t = 0; t < SS; t++) {
            unsigned int ph = (unsigned)((t & 1) * 8);
            // chain A: dot + push
            float pA = dot64(wreg, hbufA + p * 64);
            {
                unsigned int raddr = pbA_r + (unsigned)(((t & 1) * 256 + sl) * 4);
                asm volatile(
                    "st.async.shared::cluster.mbarrier::complete_tx::bytes.f32 [%0], %1, [%2];"
                    :: "r"(raddr), "f"(pA), "r"(bar_r + ph) : "memory");
            }
            // chain B: dot + push
            float pB = dot64(wreg, hbufB + p * 64);
            {
                unsigned int raddr = pbB_r + (unsigned)(((t & 1) * 256 + sl) * 4);
                asm volatile(
                    "st.async.shared::cluster.mbarrier::complete_tx::bytes.f32 [%0], %1, [%2];"
                    :: "r"(raddr), "f"(pB), "r"(bar_r + 16 + ph) : "memory");
            }
            // wait for act warps to store hA,hB of this step
            asm volatile("bar.sync 1, 512;" ::: "memory");
            p ^= 1;
        }
    }

    // keep cluster alive until both CTAs are done (peer may still push)
    asm volatile("barrier.cluster.arrive.aligned;" ::: "memory");
    asm volatile("barrier.cluster.wait.aligned;" ::: "memory");
}

// ---------- Kernel 5: classifier ----------
__global__ void cls_kernel(const float* __restrict__ W_cls,
                           const float* __restrict__ b_cls,
                           float* __restrict__ out) {
    int t = threadIdx.x;
    if (t >= BB * 5) return;
    int b = t / 5, l = t % 5;
    float s = b_cls[l];
#pragma unroll 8
    for (int k = 0; k < 256; k++) s += g_pooled[b * 256 + k] * W_cls[l * 256 + k];
    out[b * 5 + l] = s;
}

// ---------- launch ----------
extern "C" void kernel_launch(void* const* d_in, const int* in_sizes, int n_in,
                              void* d_out, int out_size) {
    const int*   word_ids   = (const int*)d_in[0];
    const int*   deps_ids   = (const int*)d_in[1];
    const float* word_table = (const float*)d_in[2];
    const float* dep_table  = (const float*)d_in[3];
    const float* Wih_f      = (const float*)d_in[4];
    const float* Whh_f      = (const float*)d_in[5];
    const float* b_f        = (const float*)d_in[6];
    const float* Wih_b      = (const float*)d_in[7];
    const float* Whh_b      = (const float*)d_in[8];
    const float* b_b        = (const float*)d_in[9];
    const float* W_cls      = (const float*)d_in[10];
    const float* b_cls      = (const float*)d_in[11];
    float* out = (float*)d_out;

    pack_w_kernel<<<(EP * NN + 255) / 256, 256>>>(Wih_f, Wih_b, b_f, b_b);
    embed_kernel<<<BB * SS, 128>>>(word_ids, deps_ids, word_table, dep_table);
    gemm_tc_kernel<<<dim3(128, 8), 256>>>();
    // 16 clusters per direction x 2 chains per cluster = 32 batches
    lstm_scan_kernel<<<dim3(32, 2), 512>>>(Whh_f, Whh_b);
    cls_kernel<<<1, 256>>>(W_cls, b_cls, out);
}

// round 14
// speedup vs baseline: 1.1683x; 1.1683x over previous
#include <cuda_runtime.h>
#include <cuda_bf16.h>
#include <cstdint>

// Problem constants
#define BB 32
#define SS 512
#define EE 300
#define EP 304          // padded K
#define HH 128
#define G4 512          // 4*H
#define NN 1024         // fused fwd+bwd gate width

// Scratch (device globals; allocation-free rule)
__device__ float g_X[(size_t)BB * SS * EP];        // padded embeddings [16384][304]
__device__ float g_W[(size_t)EP * NN];             // packed input weights W[k][n], n permuted
__device__ float g_bias[NN];
__device__ float g_G[(size_t)BB * SS * NN];        // gate preactivations [16384][1024]
__device__ float g_pooled[BB * 2 * HH];            // [b][dir*128+idx]

// Dynamic smem layout for the scan (per CTA):
//   [0, 65536)        wsp: 16 x 512 ull  (second half of weights, transposed)
//   [65536, 66048)    hbuf: 2 x 64 floats
//   [66048, 68096)    pbuf: 2 x 256 floats
//   [68096, 68112)    bars: 2 mbarriers
#define SCAN_WSP_OFF   0
#define SCAN_HBUF_OFF  65536
#define SCAN_PBUF_OFF  66048
#define SCAN_BARS_OFF  68096
#define SCAN_SMEM_BYTES 68112

// ---------- helpers ----------
__device__ __forceinline__ unsigned long long fma2(unsigned long long a,
                                                   unsigned long long b,
                                                   unsigned long long c) {
    unsigned long long d;
    asm("fma.rn.f32x2 %0, %1, %2, %3;" : "=l"(d) : "l"(a), "l"(b), "l"(c));
    return d;
}
__device__ __forceinline__ float2 unpk(unsigned long long v) {
    float2 r;
    asm("mov.b64 {%0, %1}, %2;" : "=f"(r.x), "=f"(r.y) : "l"(v));
    return r;
}
__device__ __forceinline__ float tanh_ap(float x) {
    float y;
    asm("tanh.approx.f32 %0, %1;" : "=f"(y) : "f"(x));
    return y;
}
__device__ __forceinline__ unsigned int smem_u32(const void* p) {
    unsigned int a;
    asm("{ .reg .u64 t; cvta.to.shared.u64 t, %1; cvt.u32.u64 %0, t; }"
        : "=r"(a) : "l"(p));
    return a;
}
__device__ __forceinline__ uint32_t f2tf32(float f) {
    uint32_t u;
    asm("cvt.rna.tf32.f32 %0, %1;" : "=r"(u) : "f"(f));
    return u;
}
__device__ __forceinline__ void mma_tf32(float* c,
                                         uint32_t a0, uint32_t a1, uint32_t a2, uint32_t a3,
                                         uint32_t b0, uint32_t b1) {
    asm volatile(
        "mma.sync.aligned.m16n8k8.row.col.f32.tf32.tf32.f32 "
        "{%0,%1,%2,%3}, {%4,%5,%6,%7}, {%8,%9}, {%0,%1,%2,%3};"
        : "+f"(c[0]), "+f"(c[1]), "+f"(c[2]), "+f"(c[3])
        : "r"(a0), "r"(a1), "r"(a2), "r"(a3), "r"(b0), "r"(b1));
}
// mbarrier wait (parity), acquire.cta
__device__ __forceinline__ void mbar_wait(unsigned int mb, unsigned int par) {
    unsigned int done;
    asm volatile(
        "{\n\t.reg .pred P;\n\t"
        "mbarrier.try_wait.parity.acquire.cta.shared::cta.b64 P, [%1], %2;\n\t"
        "selp.b32 %0, 1, 0, P;\n\t}"
        : "=r"(done) : "r"(mb), "r"(par) : "memory");
    if (!done) {
        asm volatile(
            "{\n\t.reg .pred P;\n"
            "WL%=:\n\t"
            "mbarrier.try_wait.parity.acquire.cta.shared::cta.b64 P, [%0], %1, 0x989680;\n\t"
            "@P bra.uni WD%=;\n\t"
            "bra.uni WL%=;\n"
            "WD%=:\n\t}"
            :: "r"(mb), "r"(par) : "memory");
    }
}
// 64-element dot: 16 f32x2 from registers (h[0..31]) + 16 f32x2 from smem
// (h[32..63]); wsp pointer is pre-offset by tid, stride 512 ull per m.
__device__ __forceinline__ float dot64_split(const unsigned long long* wreg,
                                             const unsigned long long* wsp,
                                             const float* hvec) {
    const ulonglong2* hq = (const ulonglong2*)hvec;
    unsigned long long a0 = 0ull, a1 = 0ull, a2 = 0ull, a3 = 0ull;
#pragma unroll
    for (int m = 0; m < 4; m++) {
        ulonglong2 q0 = hq[2 * m], q1 = hq[2 * m + 1];
        a0 = fma2(wreg[4 * m + 0], q0.x, a0);
        a1 = fma2(wreg[4 * m + 1], q0.y, a1);
        a2 = fma2(wreg[4 * m + 2], q1.x, a2);
        a3 = fma2(wreg[4 * m + 3], q1.y, a3);
    }
#pragma unroll
    for (int m = 0; m < 4; m++) {
        ulonglong2 q0 = hq[8 + 2 * m], q1 = hq[8 + 2 * m + 1];
        a0 = fma2(wsp[(4 * m + 0) * 512], q0.x, a0);
        a1 = fma2(wsp[(4 * m + 1) * 512], q0.y, a1);
        a2 = fma2(wsp[(4 * m + 2) * 512], q1.x, a2);
        a3 = fma2(wsp[(4 * m + 3) * 512], q1.y, a3);
    }
    float2 s0 = unpk(a0), s1 = unpk(a1), s2 = unpk(a2), s3 = unpk(a3);
    return ((s0.x + s0.y) + (s1.x + s1.y)) + ((s2.x + s2.y) + (s3.x + s3.y));
}

// ---------- Kernel 1: pack input-projection weights + bias ----------
// Column permutation: packed col n = dir*512 + hu*4 + gi.
__global__ void pack_w_kernel(const float* __restrict__ Wih_f,
                              const float* __restrict__ Wih_b,
                              const float* __restrict__ b_f,
                              const float* __restrict__ b_b) {
    int idx = blockIdx.x * 256 + threadIdx.x;
    if (idx < EP * NN) {
        int k = idx >> 10;
        int n = idx & 1023;
        int d = n >> 9, r = n & 511;
        int hu = r >> 2, gi = r & 3;
        int srow = gi * HH + hu;           // source gate row in Wih layout
        float v = 0.0f;
        if (k < EE) v = d ? Wih_b[srow * EE + k] : Wih_f[srow * EE + k];
        g_W[idx] = v;
    }
    if (idx < NN) {
        int d = idx >> 9, r = idx & 511;
        int hu = r >> 2, gi = r & 3;
        int srow = gi * HH + hu;
        g_bias[idx] = d ? b_b[srow] : b_f[srow];
    }
}

// ---------- Kernel 2: embeddings with dep-mean blend ----------
__global__ void embed_kernel(const int* __restrict__ word_ids,
                             const int* __restrict__ deps_ids,
                             const float* __restrict__ word_table,
                             const float* __restrict__ dep_table) {
    int bs = blockIdx.x;           // 0..16383
    int b = bs >> 9;
    int s = bs & 511;
    int wid = word_ids[b * (3 * SS) + SS + s];

    int ids[8];
    float cnt = 0.0f;
#pragma unroll
    for (int d = 0; d < 8; d++) {
        ids[d] = deps_ids[bs * 8 + d];
        if (ids[d] > 1) cnt += 1.0f;   // PAD=0, UNK=1
    }
    float inv = (cnt > 0.0f) ? 0.5f / cnt : 0.0f;
    float wscale = (cnt > 0.0f) ? 0.5f : 1.0f;

    for (int e = threadIdx.x; e < EP; e += 128) {
        float v = 0.0f;
        if (e < EE) {
            float w = word_table[(size_t)wid * EE + e];
            float sum = 0.0f;
#pragma unroll
            for (int d = 0; d < 8; d++) {
                if (ids[d] > 1) sum += dep_table[ids[d] * EE + e];
            }
            v = wscale * w + inv * sum;
        }
        g_X[(size_t)bs * EP + e] = v;
    }
}

// ---------- Kernel 3: tf32 tensor-core GEMM G = X @ W + bias ----------
__global__ void __launch_bounds__(256, 2) gemm_tc_kernel() {
    __shared__ uint32_t As[128][20];
    __shared__ uint32_t Bs[16][136];

    int tid = threadIdx.x;
    int bm = blockIdx.x * 128;
    int bn = blockIdx.y * 128;
    int lane = tid & 31, wid = tid >> 5;
    int wm = wid & 3, wn = wid >> 2;
    int g = lane >> 2, tg = lane & 3;

    float acc[2][8][4];
#pragma unroll
    for (int i = 0; i < 2; i++)
#pragma unroll
        for (int j = 0; j < 8; j++)
#pragma unroll
            for (int q = 0; q < 4; q++) acc[i][j][q] = 0.0f;

    int aIdx0 = tid * 2, aIdx1 = tid * 2 + 1;
    int am0 = aIdx0 >> 2, ak0 = (aIdx0 & 3) << 2;
    int am1 = aIdx1 >> 2, ak1 = (aIdx1 & 3) << 2;
    int bk0 = aIdx0 >> 5, bn0 = (aIdx0 & 31) << 2;
    int bk1 = aIdx1 >> 5, bn1 = (aIdx1 & 31) << 2;

    float4 aR0, aR1, bR0, bR1;
    aR0 = *(const float4*)(g_X + (size_t)(bm + am0) * EP + ak0);
    aR1 = *(const float4*)(g_X + (size_t)(bm + am1) * EP + ak1);
    bR0 = *(const float4*)(g_W + (size_t)bk0 * NN + bn + bn0);
    bR1 = *(const float4*)(g_W + (size_t)bk1 * NN + bn + bn1);

    for (int k0 = 0; k0 < EP; k0 += 16) {
        __syncthreads();
        {
            uint4 u;
            u.x = f2tf32(aR0.x); u.y = f2tf32(aR0.y); u.z = f2tf32(aR0.z); u.w = f2tf32(aR0.w);
            *(uint4*)&As[am0][ak0] = u;
            u.x = f2tf32(aR1.x); u.y = f2tf32(aR1.y); u.z = f2tf32(aR1.z); u.w = f2tf32(aR1.w);
            *(uint4*)&As[am1][ak1] = u;
            u.x = f2tf32(bR0.x); u.y = f2tf32(bR0.y); u.z = f2tf32(bR0.z); u.w = f2tf32(bR0.w);
            *(uint4*)&Bs[bk0][bn0] = u;
            u.x = f2tf32(bR1.x); u.y = f2tf32(bR1.y); u.z = f2tf32(bR1.z); u.w = f2tf32(bR1.w);
            *(uint4*)&Bs[bk1][bn1] = u;
        }
        __syncthreads();

        if (k0 + 16 < EP) {
            aR0 = *(const float4*)(g_X + (size_t)(bm + am0) * EP + k0 + 16 + ak0);
            aR1 = *(const float4*)(g_X + (size_t)(bm + am1) * EP + k0 + 16 + ak1);
            bR0 = *(const float4*)(g_W + (size_t)(k0 + 16 + bk0) * NN + bn + bn0);
            bR1 = *(const float4*)(g_W + (size_t)(k0 + 16 + bk1) * NN + bn + bn1);
        }

#pragma unroll
        for (int kp = 0; kp < 16; kp += 8) {
            uint32_t af[2][4];
#pragma unroll
            for (int i = 0; i < 2; i++) {
                int mr = wm * 32 + i * 16 + g;
                af[i][0] = As[mr][kp + tg];
                af[i][1] = As[mr + 8][kp + tg];
                af[i][2] = As[mr][kp + tg + 4];
                af[i][3] = As[mr + 8][kp + tg + 4];
            }
#pragma unroll
            for (int j = 0; j < 8; j++) {
                int nc = wn * 64 + j * 8 + g;
                uint32_t b0 = Bs[kp + tg][nc];
                uint32_t b1 = Bs[kp + tg + 4][nc];
#pragma unroll
                for (int i = 0; i < 2; i++)
                    mma_tf32(acc[i][j], af[i][0], af[i][1], af[i][2], af[i][3], b0, b1);
            }
        }
    }

#pragma unroll
    for (int j = 0; j < 8; j++) {
        int col = bn + wn * 64 + j * 8 + tg * 2;
        float bc0 = g_bias[col], bc1 = g_bias[col + 1];
#pragma unroll
        for (int i = 0; i < 2; i++) {
            int row = bm + wm * 32 + i * 16 + g;
            *(float2*)(g_G + (size_t)row * NN + col) =
                make_float2(acc[i][j][0] + bc0, acc[i][j][1] + bc1);
            *(float2*)(g_G + (size_t)(row + 8) * NN + col) =
                make_float2(acc[i][j][2] + bc0, acc[i][j][3] + bc1);
        }
    }
}

// ---------- Kernel 4: LSTM scan — R12 protocol, occupancy 2 ----------
// One chain per 2-CTA cluster (exactly R12's proven structure), but weights
// split 32-in-regs / 32-in-smem so regs <= 64 and TWO CTAs (two independent
// chains) co-reside per SM. The warp scheduler fills one chain's DSMEM
// latency with the other chain's issue.
__global__ void __launch_bounds__(512, 2) __cluster_dims__(2, 1, 1)
lstm_scan_kernel(const float* __restrict__ Whh_f, const float* __restrict__ Whh_b) {
    extern __shared__ unsigned char dsm[];
    unsigned long long* wsp = (unsigned long long*)(dsm + SCAN_WSP_OFF);
    float* hbuf = (float*)(dsm + SCAN_HBUF_OFF);    // [2][64]
    float* pbuf = (float*)(dsm + SCAN_PBUF_OFF);    // [2][256]
    unsigned long long* bars = (unsigned long long*)(dsm + SCAN_BARS_OFF);

    int tid = threadIdx.x;
    int l = tid & 31;
    int hu = tid >> 2;                   // global hidden unit 0..127
    int gi = tid & 3;                    // gate (i,f,g,o)

    unsigned int rank;
    asm("mov.u32 %0, %%cluster_ctarank;" : "=r"(rank));
    unsigned int peer = rank ^ 1u;

    bool own = ((unsigned)(tid >> 8) == rank);   // my row belongs to my units
    int b = blockIdx.x >> 1;
    int dir = blockIdx.y;
    const float* Whh = dir ? Whh_b : Whh_f;

    // weights for row srow, columns [rank*64, +64): 16 f32x2 in regs (h 0..31),
    // 16 f32x2 in smem (h 32..63, transposed layout wsp[m*512+tid])
    int srow = gi * HH + hu;
    const unsigned long long* wr =
        (const unsigned long long*)(Whh + (size_t)srow * HH + rank * 64);
    unsigned long long wreg[16];
#pragma unroll
    for (int m = 0; m < 16; m++) wreg[m] = wr[m];
#pragma unroll
    for (int m = 0; m < 16; m++) wsp[m * 512 + tid] = wr[16 + m];
    const unsigned long long* wspT = wsp + tid;

    if (tid < 128) hbuf[tid] = 0.0f;
    pbuf[tid] = 0.0f;                    // 512 threads cover 2*256
    if (tid == 0) {
        unsigned int b0 = smem_u32(&bars[0]);
        asm volatile("mbarrier.init.shared.b64 [%0], 1;" :: "r"(b0) : "memory");
        asm volatile("mbarrier.init.shared.b64 [%0], 1;" :: "r"(b0 + 8) : "memory");
    }
    __syncthreads();
    asm volatile("barrier.cluster.arrive.aligned;" ::: "memory");
    asm volatile("barrier.cluster.wait.aligned;" ::: "memory");

    unsigned int pb_l = smem_u32(pbuf);
    unsigned int bar_l = smem_u32(&bars[0]);
    unsigned int pb_r, bar_r;
    asm("mapa.shared::cluster.u32 %0, %1, %2;" : "=r"(pb_r) : "r"(pb_l), "r"(peer));
    asm("mapa.shared::cluster.u32 %0, %1, %2;" : "=r"(bar_r) : "r"(bar_l), "r"(peer));

    float c = 0.0f, hmax = -1e30f;

    // permuted G column = dir*512 + tid (tid == hu*4+gi)
    const float* gp = dir ? (g_G + ((size_t)(b * SS + SS - 1)) * NN + G4 + tid)
                          : (g_G + ((size_t)(b * SS)) * NN + tid);
    long stepoff = dir ? -(long)NN : (long)NN;

    float gpre = own ? __ldg(gp) : 0.0f;
    gp += stepoff;

    int p = 0;
    if (own) {
        // ======================= ACT role (my 256 rows) =======================
        int sl = tid & 255;
        for (int t = 0; t < SS; t++) {
            if (sl == 0) {
                asm volatile(
                    "mbarrier.arrive.expect_tx.shared.b64 _, [%0], 1024;"
                    :: "r"(bar_l + (unsigned)((t & 1) * 8)) : "memory");
            }

            float gnext = 0.0f;
            if (t + 1 < SS) gnext = __ldg(gp);
            gp += stepoff;

            float partial = dot64_split(wreg, wspT, hbuf + p * 64);

            // wait for peer partials of THIS step
            mbar_wait(bar_l + (unsigned)((t & 1) * 8), (t >> 1) & 1);
            float s = partial + pbuf[(t & 1) * 256 + sl] + gpre;

            // one tanh.approx per lane covers all gates
            float targ = (gi == 2) ? s : 0.5f * s;
            float tv = tanh_ap(targ);

            int base = l & ~3;           // 4-lane group = one hidden unit
            float ti = __shfl_sync(0xffffffffu, tv, base + 0);
            float tf = __shfl_sync(0xffffffffu, tv, base + 1);
            float tg = __shfl_sync(0xffffffffu, tv, base + 2);
            float to = __shfl_sync(0xffffffffu, tv, base + 3);

            float ig = fmaf(0.5f, ti, 0.5f);
            float fg = fmaf(0.5f, tf, 0.5f);
            float og = fmaf(0.5f, to, 0.5f);
            c = fg * c + ig * tg;
            float hh = og * tanh_ap(c);
            hmax = fmaxf(hmax, hh);

            if (gi == 0) hbuf[(p ^ 1) * 64 + (hu & 63)] = hh;
            // release producers (non-blocking), then act-internal rendezvous
            asm volatile("bar.arrive 1, 512;" ::: "memory");
            asm volatile("bar.sync 2, 256;" ::: "memory");
            p ^= 1;
            gpre = gnext;
        }
        if (gi == 0) g_pooled[b * 256 + dir * HH + hu] = hmax;
    } else {
        // ===================== PRODUCER role (peer's rows) =====================
        for (int t = 0; t < SS; t++) {
            float partial = dot64_split(wreg, wspT, hbuf + p * 64);

            // push partial to peer's pbuf slot; complete_tx on peer's bar[t&1]
            unsigned int raddr = pb_r + (unsigned)(((t & 1) * 256 + (tid & 255)) * 4);
            unsigned int rmbar = bar_r + (unsigned)((t & 1) * 8);
            asm volatile(
                "st.async.shared::cluster.mbarrier::complete_tx::bytes.f32 [%0], %1, [%2];"
                :: "r"(raddr), "f"(partial), "r"(rmbar) : "memory");

            // wait for act warps to store h_t (released by their bar.arrive)
            asm volatile("bar.sync 1, 512;" ::: "memory");
            p ^= 1;
        }
    }

    // keep cluster alive until both CTAs are done (peer may still push)
    asm volatile("barrier.cluster.arrive.aligned;" ::: "memory");
    asm volatile("barrier.cluster.wait.aligned;" ::: "memory");
}

// ---------- Kernel 5: classifier ----------
__global__ void cls_kernel(const float* __restrict__ W_cls,
                           const float* __restrict__ b_cls,
                           float* __restrict__ out) {
    int t = threadIdx.x;
    if (t >= BB * 5) return;
    int b = t / 5, l = t % 5;
    float s = b_cls[l];
#pragma unroll 8
    for (int k = 0; k < 256; k++) s += g_pooled[b * 256 + k] * W_cls[l * 256 + k];
    out[b * 5 + l] = s;
}

// ---------- launch ----------
extern "C" void kernel_launch(void* const* d_in, const int* in_sizes, int n_in,
                              void* d_out, int out_size) {
    const int*   word_ids   = (const int*)d_in[0];
    const int*   deps_ids   = (const int*)d_in[1];
    const float* word_table = (const float*)d_in[2];
    const float* dep_table  = (const float*)d_in[3];
    const float* Wih_f      = (const float*)d_in[4];
    const float* Whh_f      = (const float*)d_in[5];
    const float* b_f        = (const float*)d_in[6];
    const float* Wih_b      = (const float*)d_in[7];
    const float* Whh_b      = (const float*)d_in[8];
    const float* b_b        = (const float*)d_in[9];
    const float* W_cls      = (const float*)d_in[10];
    const float* b_cls      = (const float*)d_in[11];
    float* out = (float*)d_out;

    cudaFuncSetAttribute(lstm_scan_kernel,
                         cudaFuncAttributeMaxDynamicSharedMemorySize,
                         SCAN_SMEM_BYTES);

    pack_w_kernel<<<(EP * NN + 255) / 256, 256>>>(Wih_f, Wih_b, b_f, b_b);
    embed_kernel<<<BB * SS, 128>>>(word_ids, deps_ids, word_table, dep_table);
    gemm_tc_kernel<<<dim3(128, 8), 256>>>();
    // 64 clusters (32 chains x 2 dirs), 2 CTAs each; occupancy 2 -> 64 SMs
    lstm_scan_kernel<<<dim3(64, 2), 512, SCAN_SMEM_BYTES>>>(Whh_f, Whh_b);
    cls_kernel<<<1, 256>>>(W_cls, b_cls, out);
}

// round 15
// speedup vs baseline: 1.7516x; 1.4993x over previous
#include <cuda_runtime.h>
#include <cuda_bf16.h>
#include <cstdint>

// Problem constants
#define BB 32
#define SS 512
#define EE 300
#define EP 304          // padded K
#define HH 128
#define G4 512          // 4*H
#define NN 1024         // fused fwd+bwd gate width

// Scratch (device globals; allocation-free rule)
__device__ float g_X[(size_t)BB * SS * EP];        // padded embeddings [16384][304]
__device__ float g_W[(size_t)EP * NN];             // packed input weights W[k][n], n permuted
__device__ float g_bias[NN];
__device__ float g_G[(size_t)BB * SS * NN];        // gate preactivations [16384][1024]
__device__ float g_pooled[BB * 2 * HH];            // [b][dir*128+idx]

// ---------- helpers ----------
__device__ __forceinline__ unsigned long long fma2(unsigned long long a,
                                                   unsigned long long b,
                                                   unsigned long long c) {
    unsigned long long d;
    asm("fma.rn.f32x2 %0, %1, %2, %3;" : "=l"(d) : "l"(a), "l"(b), "l"(c));
    return d;
}
__device__ __forceinline__ float2 unpk(unsigned long long v) {
    float2 r;
    asm("mov.b64 {%0, %1}, %2;" : "=f"(r.x), "=f"(r.y) : "l"(v));
    return r;
}
__device__ __forceinline__ float tanh_ap(float x) {
    float y;
    asm("tanh.approx.f32 %0, %1;" : "=f"(y) : "f"(x));
    return y;
}
__device__ __forceinline__ unsigned int smem_u32(const void* p) {
    unsigned int a;
    asm("{ .reg .u64 t; cvta.to.shared.u64 t, %1; cvt.u32.u64 %0, t; }"
        : "=r"(a) : "l"(p));
    return a;
}
__device__ __forceinline__ uint32_t f2tf32(float f) {
    uint32_t u;
    asm("cvt.rna.tf32.f32 %0, %1;" : "=r"(u) : "f"(f));
    return u;
}
__device__ __forceinline__ void mma_tf32(float* c,
                                         uint32_t a0, uint32_t a1, uint32_t a2, uint32_t a3,
                                         uint32_t b0, uint32_t b1) {
    asm volatile(
        "mma.sync.aligned.m16n8k8.row.col.f32.tf32.tf32.f32 "
        "{%0,%1,%2,%3}, {%4,%5,%6,%7}, {%8,%9}, {%0,%1,%2,%3};"
        : "+f"(c[0]), "+f"(c[1]), "+f"(c[2]), "+f"(c[3])
        : "r"(a0), "r"(a1), "r"(a2), "r"(a3), "r"(b0), "r"(b1));
}
// mbarrier wait (parity), acquire.cta
__device__ __forceinline__ void mbar_wait(unsigned int mb, unsigned int par) {
    unsigned int done;
    asm volatile(
        "{\n\t.reg .pred P;\n\t"
        "mbarrier.try_wait.parity.acquire.cta.shared::cta.b64 P, [%1], %2;\n\t"
        "selp.b32 %0, 1, 0, P;\n\t}"
        : "=r"(done) : "r"(mb), "r"(par) : "memory");
    if (!done) {
        asm volatile(
            "{\n\t.reg .pred P;\n"
            "WL%=:\n\t"
            "mbarrier.try_wait.parity.acquire.cta.shared::cta.b64 P, [%0], %1, 0x989680;\n\t"
            "@P bra.uni WD%=;\n\t"
            "bra.uni WL%=;\n"
            "WD%=:\n\t}"
            :: "r"(mb), "r"(par) : "memory");
    }
}
// 32-element dot: 16 packed f32x2 register weights x contiguous h in smem
__device__ __forceinline__ float dot32(const unsigned long long* wreg,
                                       const float* hvec) {
    const ulonglong2* hq = (const ulonglong2*)hvec;
    unsigned long long a0 = 0ull, a1 = 0ull, a2 = 0ull, a3 = 0ull;
#pragma unroll
    for (int m = 0; m < 4; m++) {
        ulonglong2 q0 = hq[2 * m], q1 = hq[2 * m + 1];
        a0 = fma2(wreg[4 * m + 0], q0.x, a0);
        a1 = fma2(wreg[4 * m + 1], q0.y, a1);
        a2 = fma2(wreg[4 * m + 2], q1.x, a2);
        a3 = fma2(wreg[4 * m + 3], q1.y, a3);
    }
    float2 s0 = unpk(a0), s1 = unpk(a1), s2 = unpk(a2), s3 = unpk(a3);
    return ((s0.x + s0.y) + (s1.x + s1.y)) + ((s2.x + s2.y) + (s3.x + s3.y));
}

// ---------- Kernel 1: pack input-projection weights + bias ----------
// Column permutation: packed col n = dir*512 + hu*4 + gi.
__global__ void pack_w_kernel(const float* __restrict__ Wih_f,
                              const float* __restrict__ Wih_b,
                              const float* __restrict__ b_f,
                              const float* __restrict__ b_b) {
    int idx = blockIdx.x * 256 + threadIdx.x;
    if (idx < EP * NN) {
        int k = idx >> 10;
        int n = idx & 1023;
        int d = n >> 9, r = n & 511;
        int hu = r >> 2, gi = r & 3;
        int srow = gi * HH + hu;           // source gate row in Wih layout
        float v = 0.0f;
        if (k < EE) v = d ? Wih_b[srow * EE + k] : Wih_f[srow * EE + k];
        g_W[idx] = v;
    }
    if (idx < NN) {
        int d = idx >> 9, r = idx & 511;
        int hu = r >> 2, gi = r & 3;
        int srow = gi * HH + hu;
        g_bias[idx] = d ? b_b[srow] : b_f[srow];
    }
}

// ---------- Kernel 2: embeddings with dep-mean blend ----------
__global__ void embed_kernel(const int* __restrict__ word_ids,
                             const int* __restrict__ deps_ids,
                             const float* __restrict__ word_table,
                             const float* __restrict__ dep_table) {
    int bs = blockIdx.x;           // 0..16383
    int b = bs >> 9;
    int s = bs & 511;
    int wid = word_ids[b * (3 * SS) + SS + s];

    int ids[8];
    float cnt = 0.0f;
#pragma unroll
    for (int d = 0; d < 8; d++) {
        ids[d] = deps_ids[bs * 8 + d];
        if (ids[d] > 1) cnt += 1.0f;   // PAD=0, UNK=1
    }
    float inv = (cnt > 0.0f) ? 0.5f / cnt : 0.0f;
    float wscale = (cnt > 0.0f) ? 0.5f : 1.0f;

    for (int e = threadIdx.x; e < EP; e += 128) {
        float v = 0.0f;
        if (e < EE) {
            float w = word_table[(size_t)wid * EE + e];
            float sum = 0.0f;
#pragma unroll
            for (int d = 0; d < 8; d++) {
                if (ids[d] > 1) sum += dep_table[ids[d] * EE + e];
            }
            v = wscale * w + inv * sum;
        }
        g_X[(size_t)bs * EP + e] = v;
    }
}

// ---------- Kernel 3: tf32 tensor-core GEMM G = X @ W + bias ----------
__global__ void __launch_bounds__(256, 2) gemm_tc_kernel() {
    __shared__ uint32_t As[128][20];
    __shared__ uint32_t Bs[16][136];

    int tid = threadIdx.x;
    int bm = blockIdx.x * 128;
    int bn = blockIdx.y * 128;
    int lane = tid & 31, wid = tid >> 5;
    int wm = wid & 3, wn = wid >> 2;
    int g = lane >> 2, tg = lane & 3;

    float acc[2][8][4];
#pragma unroll
    for (int i = 0; i < 2; i++)
#pragma unroll
        for (int j = 0; j < 8; j++)
#pragma unroll
            for (int q = 0; q < 4; q++) acc[i][j][q] = 0.0f;

    int aIdx0 = tid * 2, aIdx1 = tid * 2 + 1;
    int am0 = aIdx0 >> 2, ak0 = (aIdx0 & 3) << 2;
    int am1 = aIdx1 >> 2, ak1 = (aIdx1 & 3) << 2;
    int bk0 = aIdx0 >> 5, bn0 = (aIdx0 & 31) << 2;
    int bk1 = aIdx1 >> 5, bn1 = (aIdx1 & 31) << 2;

    float4 aR0, aR1, bR0, bR1;
    aR0 = *(const float4*)(g_X + (size_t)(bm + am0) * EP + ak0);
    aR1 = *(const float4*)(g_X + (size_t)(bm + am1) * EP + ak1);
    bR0 = *(const float4*)(g_W + (size_t)bk0 * NN + bn + bn0);
    bR1 = *(const float4*)(g_W + (size_t)bk1 * NN + bn + bn1);

    for (int k0 = 0; k0 < EP; k0 += 16) {
        __syncthreads();
        {
            uint4 u;
            u.x = f2tf32(aR0.x); u.y = f2tf32(aR0.y); u.z = f2tf32(aR0.z); u.w = f2tf32(aR0.w);
            *(uint4*)&As[am0][ak0] = u;
            u.x = f2tf32(aR1.x); u.y = f2tf32(aR1.y); u.z = f2tf32(aR1.z); u.w = f2tf32(aR1.w);
            *(uint4*)&As[am1][ak1] = u;
            u.x = f2tf32(bR0.x); u.y = f2tf32(bR0.y); u.z = f2tf32(bR0.z); u.w = f2tf32(bR0.w);
            *(uint4*)&Bs[bk0][bn0] = u;
            u.x = f2tf32(bR1.x); u.y = f2tf32(bR1.y); u.z = f2tf32(bR1.z); u.w = f2tf32(bR1.w);
            *(uint4*)&Bs[bk1][bn1] = u;
        }
        __syncthreads();

        if (k0 + 16 < EP) {
            aR0 = *(const float4*)(g_X + (size_t)(bm + am0) * EP + k0 + 16 + ak0);
            aR1 = *(const float4*)(g_X + (size_t)(bm + am1) * EP + k0 + 16 + ak1);
            bR0 = *(const float4*)(g_W + (size_t)(k0 + 16 + bk0) * NN + bn + bn0);
            bR1 = *(const float4*)(g_W + (size_t)(k0 + 16 + bk1) * NN + bn + bn1);
        }

#pragma unroll
        for (int kp = 0; kp < 16; kp += 8) {
            uint32_t af[2][4];
#pragma unroll
            for (int i = 0; i < 2; i++) {
                int mr = wm * 32 + i * 16 + g;
                af[i][0] = As[mr][kp + tg];
                af[i][1] = As[mr + 8][kp + tg];
                af[i][2] = As[mr][kp + tg + 4];
                af[i][3] = As[mr + 8][kp + tg + 4];
            }
#pragma unroll
            for (int j = 0; j < 8; j++) {
                int nc = wn * 64 + j * 8 + g;
                uint32_t b0 = Bs[kp + tg][nc];
                uint32_t b1 = Bs[kp + tg + 4][nc];
#pragma unroll
                for (int i = 0; i < 2; i++)
                    mma_tf32(acc[i][j], af[i][0], af[i][1], af[i][2], af[i][3], b0, b1);
            }
        }
    }

#pragma unroll
    for (int j = 0; j < 8; j++) {
        int col = bn + wn * 64 + j * 8 + tg * 2;
        float bc0 = g_bias[col], bc1 = g_bias[col + 1];
#pragma unroll
        for (int i = 0; i < 2; i++) {
            int row = bm + wm * 32 + i * 16 + g;
            *(float2*)(g_G + (size_t)row * NN + col) =
                make_float2(acc[i][j][0] + bc0, acc[i][j][1] + bc1);
            *(float2*)(g_G + (size_t)(row + 8) * NN + col) =
                make_float2(acc[i][j][2] + bc0, acc[i][j][3] + bc1);
        }
    }
}

// ---------- Kernel 4: LSTM scan — 4-CTA cluster, 32-wide register dots ----------
// Each chain (batch,dir) = one 4-CTA cluster. CTA rank owns h-units
// [rank*32,+32). Thread tid owns gate row r=tid (permuted hu*4+gi) and holds
// 32 register weights (columns [rank*32,+32)). Act threads (tid>>7==rank, 4
// warps) sum own partial + 3 pushed peer partials + gpre, activate, store h
// locally. Producer threads push their partial to their single fixed target
// CTA. R12's arm/push/wait/role-barrier protocol, 3 sources per barrier.
// ~60 regs/thread -> 2 CTAs (2 different chains) co-reside per SM.
__global__ void __launch_bounds__(512, 2) __cluster_dims__(4, 1, 1)
lstm_scan_kernel(const float* __restrict__ Whh_f, const float* __restrict__ Whh_b) {
    __shared__ float hbuf[2 * 32];       // local units' h, double-buffered
    __shared__ float pbuf[2 * 384];      // peer partials for my 128 rows x3 sources
    __shared__ __align__(8) unsigned long long bars[2];

    int tid = threadIdx.x;
    int l = tid & 31;

    unsigned int rank;
    asm("mov.u32 %0, %%cluster_ctarank;" : "=r"(rank));

    bool own = ((unsigned)(tid >> 7) == rank);
    int b = blockIdx.x >> 2;
    int dir = blockIdx.y;
    const float* Whh = dir ? Whh_b : Whh_f;

    // 32 register-resident weights: row srow, columns [rank*32, +32)
    int hu = tid >> 2, gi = tid & 3;
    int srow = gi * HH + hu;
    const unsigned long long* wr =
        (const unsigned long long*)(Whh + (size_t)srow * HH + rank * 32);
    unsigned long long wreg[16];
#pragma unroll
    for (int m = 0; m < 16; m++) wreg[m] = wr[m];

    if (tid < 64) hbuf[tid] = 0.0f;
    if (tid == 0) {
        unsigned int b0 = smem_u32(&bars[0]);
        asm volatile("mbarrier.init.shared.b64 [%0], 1;" :: "r"(b0) : "memory");
        asm volatile("mbarrier.init.shared.b64 [%0], 1;" :: "r"(b0 + 8) : "memory");
    }
    __syncthreads();
    asm volatile("barrier.cluster.arrive.aligned;" ::: "memory");
    asm volatile("barrier.cluster.wait.aligned;" ::: "memory");

    unsigned int bar_l = smem_u32(&bars[0]);
    // producer: remote addresses for my single target CTA q = tid>>7
    unsigned int pb_r = 0, bar_r = 0;
    if (!own) {
        unsigned int q = (unsigned)(tid >> 7);
        unsigned int pb_l = smem_u32(pbuf);
        asm("mapa.shared::cluster.u32 %0, %1, %2;" : "=r"(pb_r) : "r"(pb_l), "r"(q));
        asm("mapa.shared::cluster.u32 %0, %1, %2;" : "=r"(bar_r) : "r"(bar_l), "r"(q));
        // source index of my rank among q's 3 sources (ranks != q, ascending)
        unsigned int srci = rank - (rank > q ? 1u : 0u);
        pb_r += (srci * 128 + (unsigned)(tid & 127)) * 4;
    }

    float c = 0.0f, hmax = -1e30f;

    // permuted G column = dir*512 + tid
    const float* gp = dir ? (g_G + ((size_t)(b * SS + SS - 1)) * NN + G4 + tid)
                          : (g_G + ((size_t)(b * SS)) * NN + tid);
    long stepoff = dir ? -(long)NN : (long)NN;

    float gpre = own ? __ldg(gp) : 0.0f;
    gp += stepoff;

    int p = 0;
    if (own) {
        // ======================= ACT role (my 128 rows) =======================
        int sl = tid & 127;
        for (int t = 0; t < SS; t++) {
            // arm: 1 arrival + 3*128*4 = 1536 bytes from the 3 source CTAs
            if (sl == 0) {
                asm volatile(
                    "mbarrier.arrive.expect_tx.shared.b64 _, [%0], 1536;"
                    :: "r"(bar_l + (unsigned)((t & 1) * 8)) : "memory");
            }

            float gnext = 0.0f;
            if (t + 1 < SS) gnext = __ldg(gp);
            gp += stepoff;

            // own partial dot over my 32 local h values
            float partial = dot32(wreg, hbuf + p * 32);

            // wait for the 3 peer partials of THIS step
            mbar_wait(bar_l + (unsigned)((t & 1) * 8), (t >> 1) & 1);
            int pbase = (t & 1) * 384 + sl;
            float s = partial + pbuf[pbase] + pbuf[pbase + 128]
                    + pbuf[pbase + 256] + gpre;

            // one tanh.approx per lane covers all gates
            float targ = (gi == 2) ? s : 0.5f * s;
            float tv = tanh_ap(targ);

            int base = l & ~3;           // 4-lane group = one hidden unit
            float ti = __shfl_sync(0xffffffffu, tv, base + 0);
            float tf = __shfl_sync(0xffffffffu, tv, base + 1);
            float tg = __shfl_sync(0xffffffffu, tv, base + 2);
            float to = __shfl_sync(0xffffffffu, tv, base + 3);

            float ig = fmaf(0.5f, ti, 0.5f);
            float fg = fmaf(0.5f, tf, 0.5f);
            float og = fmaf(0.5f, to, 0.5f);
            c = fg * c + ig * tg;
            float hh = og * tanh_ap(c);
            hmax = fmaxf(hmax, hh);

            if (gi == 0) hbuf[(p ^ 1) * 32 + (hu & 31)] = hh;
            // release producers (non-blocking), then act-internal rendezvous
            asm volatile("bar.arrive 1, 512;" ::: "memory");
            asm volatile("bar.sync 2, 128;" ::: "memory");
            p ^= 1;
            gpre = gnext;
        }
        if (gi == 0) g_pooled[b * 256 + dir * HH + hu] = hmax;
    } else {
        // ===================== PRODUCER role (other CTAs' rows) =====================
        for (int t = 0; t < SS; t++) {
            float partial = dot32(wreg, hbuf + p * 32);

            // push partial to my target CTA's pbuf slot
            unsigned int raddr = pb_r + (unsigned)((t & 1) * 384 * 4);
            unsigned int rmbar = bar_r + (unsigned)((t & 1) * 8);
            asm volatile(
                "st.async.shared::cluster.mbarrier::complete_tx::bytes.f32 [%0], %1, [%2];"
                :: "r"(raddr), "f"(partial), "r"(rmbar) : "memory");

            // wait for act warps to store h_t (released by their bar.arrive)
            asm volatile("bar.sync 1, 512;" ::: "memory");
            p ^= 1;
        }
    }

    // keep cluster alive until all CTAs are done (peers may still push)
    asm volatile("barrier.cluster.arrive.aligned;" ::: "memory");
    asm volatile("barrier.cluster.wait.aligned;" ::: "memory");
}

// ---------- Kernel 5: classifier ----------
__global__ void cls_kernel(const float* __restrict__ W_cls,
                           const float* __restrict__ b_cls,
                           float* __restrict__ out) {
    int t = threadIdx.x;
    if (t >= BB * 5) return;
    int b = t / 5, l = t % 5;
    float s = b_cls[l];
#pragma unroll 8
    for (int k = 0; k < 256; k++) s += g_pooled[b * 256 + k] * W_cls[l * 256 + k];
    out[b * 5 + l] = s;
}

// ---------- launch ----------
extern "C" void kernel_launch(void* const* d_in, const int* in_sizes, int n_in,
                              void* d_out, int out_size) {
    const int*   word_ids   = (const int*)d_in[0];
    const int*   deps_ids   = (const int*)d_in[1];
    const float* word_table = (const float*)d_in[2];
    const float* dep_table  = (const float*)d_in[3];
    const float* Wih_f      = (const float*)d_in[4];
    const float* Whh_f      = (const float*)d_in[5];
    const float* b_f        = (const float*)d_in[6];
    const float* Wih_b      = (const float*)d_in[7];
    const float* Whh_b      = (const float*)d_in[8];
    const float* b_b        = (const float*)d_in[9];
    const float* W_cls      = (const float*)d_in[10];
    const float* b_cls      = (const float*)d_in[11];
    float* out = (float*)d_out;

    pack_w_kernel<<<(EP * NN + 255) / 256, 256>>>(Wih_f, Wih_b, b_f, b_b);
    embed_kernel<<<BB * SS, 128>>>(word_ids, deps_ids, word_table, dep_table);
    gemm_tc_kernel<<<dim3(128, 8), 256>>>();
    // 32 chains x 4 cluster CTAs on x, 2 dirs on y = 256 CTAs, occ 2
    lstm_scan_kernel<<<dim3(128, 2), 512>>>(Whh_f, Whh_b);
    cls_kernel<<<1, 256>>>(W_cls, b_cls, out);
}

// round 16
// speedup vs baseline: 2.1280x; 1.2149x over previous
#include <cuda_runtime.h>
#include <cuda_bf16.h>
#include <cuda_fp16.h>
#include <cstdint>

// Problem constants
#define BB 32
#define SS 512
#define EE 300
#define EP 304          // padded K
#define EPH 152         // EP/2 (packed half2 words per row)
#define HH 128
#define G4 512          // 4*H
#define NN 1024         // fused fwd+bwd gate width

// Scratch (device globals; allocation-free rule)
__device__ __align__(16) __half g_X[(size_t)BB * SS * EP];  // fp16 embeddings [16384][304]
__device__ uint32_t g_Wp[(size_t)EPH * NN];   // packed half2 weights: word k2,n = (W[2k2][n], W[2k2+1][n])
__device__ float g_bias[NN];
__device__ float g_G[(size_t)BB * SS * NN];   // gate preactivations [16384][1024]
__device__ float g_pooled[BB * 2 * HH];       // [b][dir*128+idx]

// ---------- helpers ----------
__device__ __forceinline__ unsigned long long fma2(unsigned long long a,
                                                   unsigned long long b,
                                                   unsigned long long c) {
    unsigned long long d;
    asm("fma.rn.f32x2 %0, %1, %2, %3;" : "=l"(d) : "l"(a), "l"(b), "l"(c));
    return d;
}
__device__ __forceinline__ float2 unpk(unsigned long long v) {
    float2 r;
    asm("mov.b64 {%0, %1}, %2;" : "=f"(r.x), "=f"(r.y) : "l"(v));
    return r;
}
__device__ __forceinline__ float tanh_ap(float x) {
    float y;
    asm("tanh.approx.f32 %0, %1;" : "=f"(y) : "f"(x));
    return y;
}
__device__ __forceinline__ unsigned int smem_u32(const void* p) {
    unsigned int a;
    asm("{ .reg .u64 t; cvta.to.shared.u64 t, %1; cvt.u32.u64 %0, t; }"
        : "=r"(a) : "l"(p));
    return a;
}
__device__ __forceinline__ void mma_f16(float* c,
                                        uint32_t a0, uint32_t a1, uint32_t a2, uint32_t a3,
                                        uint32_t b0, uint32_t b1) {
    asm volatile(
        "mma.sync.aligned.m16n8k16.row.col.f32.f16.f16.f32 "
        "{%0,%1,%2,%3}, {%4,%5,%6,%7}, {%8,%9}, {%0,%1,%2,%3};"
        : "+f"(c[0]), "+f"(c[1]), "+f"(c[2]), "+f"(c[3])
        : "r"(a0), "r"(a1), "r"(a2), "r"(a3), "r"(b0), "r"(b1));
}
// mbarrier wait (parity), acquire.cta
__device__ __forceinline__ void mbar_wait(unsigned int mb, unsigned int par) {
    unsigned int done;
    asm volatile(
        "{\n\t.reg .pred P;\n\t"
        "mbarrier.try_wait.parity.acquire.cta.shared::cta.b64 P, [%1], %2;\n\t"
        "selp.b32 %0, 1, 0, P;\n\t}"
        : "=r"(done) : "r"(mb), "r"(par) : "memory");
    if (!done) {
        asm volatile(
            "{\n\t.reg .pred P;\n"
            "WL%=:\n\t"
            "mbarrier.try_wait.parity.acquire.cta.shared::cta.b64 P, [%0], %1, 0x989680;\n\t"
            "@P bra.uni WD%=;\n\t"
            "bra.uni WL%=;\n"
            "WD%=:\n\t}"
            :: "r"(mb), "r"(par) : "memory");
    }
}

// ---------- Kernel 1: pack input-projection weights (half2 pairs) + bias ----------
// Column permutation: packed col n = dir*512 + hu*4 + gi.
// g_Wp[k2*NN+n] packs (W[2k2][n], W[2k2+1][n]) as half2 (low = even k).
__global__ void pack_w_kernel(const float* __restrict__ Wih_f,
                              const float* __restrict__ Wih_b,
                              const float* __restrict__ b_f,
                              const float* __restrict__ b_b) {
    int idx = blockIdx.x * 256 + threadIdx.x;
    if (idx < EPH * NN) {
        int k2 = idx >> 10;                // 0..151
        int n = idx & 1023;
        int d = n >> 9, r = n & 511;
        int hu = r >> 2, gi = r & 3;
        int srow = gi * HH + hu;           // source gate row in Wih layout
        const float* Wsrc = d ? Wih_b : Wih_f;
        int k0 = 2 * k2, k1 = k0 + 1;
        float v0 = (k0 < EE) ? Wsrc[srow * EE + k0] : 0.0f;
        float v1 = (k1 < EE) ? Wsrc[srow * EE + k1] : 0.0f;
        __half2 h2 = __floats2half2_rn(v0, v1);
        g_Wp[idx] = *(uint32_t*)&h2;
    }
    if (idx < NN) {
        int d = idx >> 9, r = idx & 511;
        int hu = r >> 2, gi = r & 3;
        int srow = gi * HH + hu;
        g_bias[idx] = d ? b_b[srow] : b_f[srow];
    }
}

// ---------- Kernel 2: embeddings with dep-mean blend (fp16 output) ----------
__global__ void embed_kernel(const int* __restrict__ word_ids,
                             const int* __restrict__ deps_ids,
                             const float* __restrict__ word_table,
                             const float* __restrict__ dep_table) {
    int bs = blockIdx.x;           // 0..16383
    int b = bs >> 9;
    int s = bs & 511;
    int wid = word_ids[b * (3 * SS) + SS + s];

    int ids[8];
    float cnt = 0.0f;
#pragma unroll
    for (int d = 0; d < 8; d++) {
        ids[d] = deps_ids[bs * 8 + d];
        if (ids[d] > 1) cnt += 1.0f;   // PAD=0, UNK=1
    }
    float inv = (cnt > 0.0f) ? 0.5f / cnt : 0.0f;
    float wscale = (cnt > 0.0f) ? 0.5f : 1.0f;

    for (int e = threadIdx.x; e < EP; e += 128) {
        float v = 0.0f;
        if (e < EE) {
            float w = word_table[(size_t)wid * EE + e];
            float sum = 0.0f;
#pragma unroll
            for (int d = 0; d < 8; d++) {
                if (ids[d] > 1) sum += dep_table[ids[d] * EE + e];
            }
            v = wscale * w + inv * sum;
        }
        g_X[(size_t)bs * EP + e] = __float2half(v);
    }
}

// ---------- Kernel 3: fp16 tensor-core GEMM G = X @ W + bias ----------
// M=16384, N=1024, K=304. CTA tile 128x128, BK=16 (one m16n8k16 per frag pair).
// fp16 has the same 11-bit mantissa as tf32 -> identical precision, 2x rate.
__global__ void __launch_bounds__(256, 2) gemm_tc_kernel() {
    __shared__ uint32_t As[128][12];   // [m][k2] (8 words + pad 4)
    __shared__ uint32_t Bs[8][132];    // [k2][n] (128 + pad 4)

    int tid = threadIdx.x;
    int bm = blockIdx.x * 128;
    int bn = blockIdx.y * 128;
    int lane = tid & 31, wid = tid >> 5;
    int wm = wid & 3, wn = wid >> 2;
    int g = lane >> 2, tg = lane & 3;

    float acc[2][8][4];
#pragma unroll
    for (int i = 0; i < 2; i++)
#pragma unroll
        for (int j = 0; j < 8; j++)
#pragma unroll
            for (int q = 0; q < 4; q++) acc[i][j][q] = 0.0f;

    // load mappings: A tile 128x8 words (uint4 per thread), B tile 8x128 words
    int arow = tid >> 1, akq = (tid & 1) * 4;
    int bkr = tid >> 5, bnc = (tid & 31) * 4;
    const uint32_t* X32 = (const uint32_t*)g_X;

    uint4 aR = *(const uint4*)(X32 + (size_t)(bm + arow) * EPH + akq);
    uint4 bR = *(const uint4*)(g_Wp + (size_t)bkr * NN + bn + bnc);

    for (int kh = 0; kh < EPH; kh += 8) {
        __syncthreads();   // previous compute done before smem overwrite
        *(uint4*)&As[arow][akq] = aR;
        *(uint4*)&Bs[bkr][bnc] = bR;
        __syncthreads();

        // prefetch next tile
        if (kh + 8 < EPH) {
            aR = *(const uint4*)(X32 + (size_t)(bm + arow) * EPH + kh + 8 + akq);
            bR = *(const uint4*)(g_Wp + (size_t)(kh + 8 + bkr) * NN + bn + bnc);
        }

        uint32_t af[2][4];
#pragma unroll
        for (int i = 0; i < 2; i++) {
            int mr = wm * 32 + i * 16 + g;
            af[i][0] = As[mr][tg];
            af[i][1] = As[mr + 8][tg];
            af[i][2] = As[mr][tg + 4];
            af[i][3] = As[mr + 8][tg + 4];
        }
#pragma unroll
        for (int j = 0; j < 8; j++) {
            int nc = wn * 64 + j * 8 + g;
            uint32_t b0 = Bs[tg][nc];
            uint32_t b1 = Bs[tg + 4][nc];
#pragma unroll
            for (int i = 0; i < 2; i++)
                mma_f16(acc[i][j], af[i][0], af[i][1], af[i][2], af[i][3], b0, b1);
        }
    }

    // epilogue: add bias, store
#pragma unroll
    for (int j = 0; j < 8; j++) {
        int col = bn + wn * 64 + j * 8 + tg * 2;
        float bc0 = g_bias[col], bc1 = g_bias[col + 1];
#pragma unroll
        for (int i = 0; i < 2; i++) {
            int row = bm + wm * 32 + i * 16 + g;
            *(float2*)(g_G + (size_t)row * NN + col) =
                make_float2(acc[i][j][0] + bc0, acc[i][j][1] + bc1);
            *(float2*)(g_G + (size_t)(row + 8) * NN + col) =
                make_float2(acc[i][j][2] + bc0, acc[i][j][3] + bc1);
        }
    }
}

// ---------- Kernel 4: LSTM scan — column-split partial exchange (R12, best) ----------
// 2-CTA cluster per chain; act threads store h, bar.arrive(1) releases
// producers, bar.sync(2) among act warps only; producers bar.sync(1) then
// dot+push. mbarrier carries the producer->act dependency.
__global__ void __launch_bounds__(512, 1) __cluster_dims__(2, 1, 1)
lstm_scan_kernel(const float* __restrict__ Whh_f, const float* __restrict__ Whh_b) {
    __shared__ float hbuf[2 * 64];       // local units' h, double-buffered
    __shared__ float pbuf[2 * 256];      // peer partials for my 256 rows
    __shared__ __align__(8) unsigned long long bars[2];

    int tid = threadIdx.x;
    int l = tid & 31;
    int hu = tid >> 2;                   // global hidden unit 0..127
    int gi = tid & 3;                    // gate (i,f,g,o)

    unsigned int rank;
    asm("mov.u32 %0, %%cluster_ctarank;" : "=r"(rank));
    unsigned int peer = rank ^ 1u;

    bool own = ((unsigned)(tid >> 8) == rank);   // my row belongs to my units
    int b = blockIdx.x >> 1;
    int dir = blockIdx.y;
    const float* Whh = dir ? Whh_b : Whh_f;

    // 64 register-resident weights: row srow, columns [rank*64, +64)
    int srow = gi * HH + hu;
    const unsigned long long* wr =
        (const unsigned long long*)(Whh + (size_t)srow * HH + rank * 64);
    unsigned long long wreg[32];
#pragma unroll
    for (int m = 0; m < 32; m++) wreg[m] = wr[m];

    if (tid < 128) hbuf[tid] = 0.0f;
    pbuf[tid] = 0.0f;                    // 512 threads cover 2*256
    if (tid == 0) {
        unsigned int b0 = smem_u32(&bars[0]);
        asm volatile("mbarrier.init.shared.b64 [%0], 1;" :: "r"(b0) : "memory");
        asm volatile("mbarrier.init.shared.b64 [%0], 1;" :: "r"(b0 + 8) : "memory");
    }
    __syncthreads();
    asm volatile("barrier.cluster.arrive.aligned;" ::: "memory");
    asm volatile("barrier.cluster.wait.aligned;" ::: "memory");

    unsigned int pb_l = smem_u32(pbuf);
    unsigned int bar_l = smem_u32(&bars[0]);
    unsigned int pb_r, bar_r;
    asm("mapa.shared::cluster.u32 %0, %1, %2;" : "=r"(pb_r) : "r"(pb_l), "r"(peer));
    asm("mapa.shared::cluster.u32 %0, %1, %2;" : "=r"(bar_r) : "r"(bar_l), "r"(peer));

    float c = 0.0f, hmax = -1e30f;

    // permuted G column = dir*512 + tid (tid == hu*4+gi)
    const float* gp = dir ? (g_G + ((size_t)(b * SS + SS - 1)) * NN + G4 + tid)
                          : (g_G + ((size_t)(b * SS)) * NN + tid);
    long stepoff = dir ? -(long)NN : (long)NN;

    float gpre = own ? __ldg(gp) : 0.0f;
    gp += stepoff;

    int p = 0;
    if (own) {
        // ======================= ACT role (my 256 rows) =======================
        for (int t = 0; t < SS; t++) {
            if ((tid & 255) == 0) {
                asm volatile(
                    "mbarrier.arrive.expect_tx.shared.b64 _, [%0], 1024;"
                    :: "r"(bar_l + (unsigned)((t & 1) * 8)) : "memory");
            }

            float gnext = 0.0f;
            if (t + 1 < SS) gnext = __ldg(gp);
            gp += stepoff;

            // own partial dot over the 64 LOCAL h values
            const ulonglong2* hq = (const ulonglong2*)(hbuf + p * 64);
            unsigned long long a0 = 0ull, a1 = 0ull, a2 = 0ull, a3 = 0ull;
#pragma unroll
            for (int m = 0; m < 8; m++) {
                ulonglong2 q0 = hq[2 * m], q1 = hq[2 * m + 1];
                a0 = fma2(wreg[4 * m + 0], q0.x, a0);
                a1 = fma2(wreg[4 * m + 1], q0.y, a1);
                a2 = fma2(wreg[4 * m + 2], q1.x, a2);
                a3 = fma2(wreg[4 * m + 3], q1.y, a3);
            }
            float2 s0 = unpk(a0), s1 = unpk(a1), s2 = unpk(a2), s3 = unpk(a3);
            float partial = ((s0.x + s0.y) + (s1.x + s1.y))
                          + ((s2.x + s2.y) + (s3.x + s3.y));

            // wait for peer partials of THIS step
            mbar_wait(bar_l + (unsigned)((t & 1) * 8), (t >> 1) & 1);
            float s = partial + pbuf[(t & 1) * 256 + (tid & 255)] + gpre;

            // one tanh.approx per lane covers all gates
            float targ = (gi == 2) ? s : 0.5f * s;
            float tv = tanh_ap(targ);

            int base = l & ~3;           // 4-lane group = one hidden unit
            float ti = __shfl_sync(0xffffffffu, tv, base + 0);
            float tf = __shfl_sync(0xffffffffu, tv, base + 1);
            float tg = __shfl_sync(0xffffffffu, tv, base + 2);
            float to = __shfl_sync(0xffffffffu, tv, base + 3);

            float ig = fmaf(0.5f, ti, 0.5f);
            float fg = fmaf(0.5f, tf, 0.5f);
            float og = fmaf(0.5f, to, 0.5f);
            c = fg * c + ig * tg;
            float hh = og * tanh_ap(c);
            hmax = fmaxf(hmax, hh);

            if (gi == 0) hbuf[(p ^ 1) * 64 + (hu & 63)] = hh;
            // release producers (non-blocking), then act-internal rendezvous
            asm volatile("bar.arrive 1, 512;" ::: "memory");
            asm volatile("bar.sync 2, 256;" ::: "memory");
            p ^= 1;
            gpre = gnext;
        }
        if (gi == 0) g_pooled[b * 256 + dir * HH + hu] = hmax;
    } else {
        // ===================== PRODUCER role (peer's rows) =====================
        for (int t = 0; t < SS; t++) {
            const ulonglong2* hq = (const ulonglong2*)(hbuf + p * 64);
            unsigned long long a0 = 0ull, a1 = 0ull, a2 = 0ull, a3 = 0ull;
#pragma unroll
            for (int m = 0; m < 8; m++) {
                ulonglong2 q0 = hq[2 * m], q1 = hq[2 * m + 1];
                a0 = fma2(wreg[4 * m + 0], q0.x, a0);
                a1 = fma2(wreg[4 * m + 1], q0.y, a1);
                a2 = fma2(wreg[4 * m + 2], q1.x, a2);
                a3 = fma2(wreg[4 * m + 3], q1.y, a3);
            }
            float2 s0 = unpk(a0), s1 = unpk(a1), s2 = unpk(a2), s3 = unpk(a3);
            float partial = ((s0.x + s0.y) + (s1.x + s1.y))
                          + ((s2.x + s2.y) + (s3.x + s3.y));

            // push partial to peer's pbuf slot; complete_tx on peer's bar[t&1]
            unsigned int raddr = pb_r + (unsigned)(((t & 1) * 256 + (tid & 255)) * 4);
            unsigned int rmbar = bar_r + (unsigned)((t & 1) * 8);
            asm volatile(
                "st.async.shared::cluster.mbarrier::complete_tx::bytes.f32 [%0], %1, [%2];"
                :: "r"(raddr), "f"(partial), "r"(rmbar) : "memory");

            // wait for act warps to store h_t (released by their bar.arrive)
            asm volatile("bar.sync 1, 512;" ::: "memory");
            p ^= 1;
        }
    }

    // keep cluster alive until both CTAs are done (peer may still push)
    asm volatile("barrier.cluster.arrive.aligned;" ::: "memory");
    asm volatile("barrier.cluster.wait.aligned;" ::: "memory");
}

// ---------- Kernel 5: classifier ----------
__global__ void cls_kernel(const float* __restrict__ W_cls,
                           const float* __restrict__ b_cls,
                           float* __restrict__ out) {
    int t = threadIdx.x;
    if (t >= BB * 5) return;
    int b = t / 5, l = t % 5;
    float s = b_cls[l];
#pragma unroll 8
    for (int k = 0; k < 256; k++) s += g_pooled[b * 256 + k] * W_cls[l * 256 + k];
    out[b * 5 + l] = s;
}

// ---------- launch ----------
extern "C" void kernel_launch(void* const* d_in, const int* in_sizes, int n_in,
                              void* d_out, int out_size) {
    const int*   word_ids   = (const int*)d_in[0];
    const int*   deps_ids   = (const int*)d_in[1];
    const float* word_table = (const float*)d_in[2];
    const float* dep_table  = (const float*)d_in[3];
    const float* Wih_f      = (const float*)d_in[4];
    const float* Whh_f      = (const float*)d_in[5];
    const float* b_f        = (const float*)d_in[6];
    const float* Wih_b      = (const float*)d_in[7];
    const float* Whh_b      = (const float*)d_in[8];
    const float* b_b        = (const float*)d_in[9];
    const float* W_cls      = (const float*)d_in[10];
    const float* b_cls      = (const float*)d_in[11];
    float* out = (float*)d_out;

    pack_w_kernel<<<(EPH * NN + 255) / 256, 256>>>(Wih_f, Wih_b, b_f, b_b);
    embed_kernel<<<BB * SS, 128>>>(word_ids, deps_ids, word_table, dep_table);
    gemm_tc_kernel<<<dim3(128, 8), 256>>>();
    // 32 chains x 2 cluster CTAs on x, 2 dirs on y = 128 CTAs
    lstm_scan_kernel<<<dim3(64, 2), 512>>>(Whh_f, Whh_b);
    cls_kernel<<<1, 256>>>(W_cls, b_cls, out);
}